// round 16
// baseline (speedup 1.0000x reference)
#include <cuda_runtime.h>
#include <math.h>

#define C_B  8
#define C_J  22
#define C_F  14
#define A_MAX 7.25f
#define S_MAX 9.25f
#define SIG_K (3.14f / (1.732f * 0.5f))

// FINAL CHAMPION — record holder (bench 5.088us, R13). Single CTA, 256
// threads, warp b = batch b. Lane layout:
//   lanes 0..10  : attacker j=lane    -> r = rec_j * p_j  (sum half)
//   lanes 16..26 : defender j=lane-5  -> r = 1 - p_j      (product half)
//   lanes 11..15 neutral 0, lanes 27..31 neutral 1.
// Mixed-op butterfly: 4 levels inside each 16-lane half (add low / mul
// high) + one cross-half shuffle = 5 SHFLs for the full (sum, product)
// reduction. Sigmoid = 0.5*tanh.approx(x/2)+0.5 (single MUFU trip).
// Floor model (validated R12-R15): ~3.3us launch/ramp + ~0.4us cold DRAM
// round-trip + ~0.5us work. Identical-binary noise: ncu [4.35,4.86],
// bench [5.09,6.05]. Measured rejections: multi-CTA (+1.0us), 4 heavy
// warps (+1.1us); all other variants sub-noise. Do not mutate.
__device__ __forceinline__ float fast_sigmoid(float x) {
    float t;
    asm("tanh.approx.f32 %0, %1;" : "=f"(t) : "f"(0.5f * x));
    return fmaf(0.5f, t, 0.5f);
}

__global__ void __launch_bounds__(256, 1)
comp_prob_kernel(const float* __restrict__ frame, float* __restrict__ out) {
    const int b    = threadIdx.x >> 5;   // warp = batch
    const int lane = threadIdx.x & 31;
    const bool lowHalf = lane < 16;
    // player index: attackers 0..10 in lanes 0..10, defenders 11..21 in 16..26
    const int j = lowHalf ? lane : (lane - 5);
    const bool active = lowHalf ? (lane < 11) : (lane < 27);

    const float* row0 = frame + b * C_J * C_F;

    float r = lowHalf ? 0.0f : 1.0f;   // neutral: add-identity / mul-identity

    if (active) {
        const float* row = row0 + j * C_F;

        const float px = __ldg(row + 1), py = __ldg(row + 2);
        const float vx = __ldg(row + 3), vy = __ldg(row + 4);
        const float rec = lowHalf ? __ldg(row + 10) : 0.0f;
        const float bxf = __ldg(row0 + 11);
        const float byf = __ldg(row0 + 12);
        const float tof = __ldg(row0 + 13);

        // Selected field cell: x = int(bx)+0.5, y = (int(by)+1)-0.5
        const float fx = (float)((int)bxf) + 0.5f;
        const float fy = (float)((int)byf) + 0.5f;

        const float dx = fx - px;
        const float dy = fy - py;
        const float d2 = fmaf(dx, dx, dy * dy);
        const float invd = rsqrtf(d2);
        const float d = d2 * invd;

        float s0 = fmaf(dx, vx, dy * vy) * invd;
        s0 = fminf(fmaxf(s0, -S_MAX), S_MAX);

        // Arm A: reaches top speed
        const float t_lt1 = (S_MAX - s0) * (1.0f / A_MAX);
        const float d_lt1 = t_lt1 * (s0 + S_MAX) * 0.5f;
        // Arm B: doesn't
        const float sa = s0 * (1.0f / A_MAX);
        const float t_lt2 = sqrtf(fmaf(sa, sa, 2.0f * d * (1.0f / A_MAX))) - sa;

        const float t_lt = (d_lt1 > d) ? t_lt2 : t_lt1;
        const float d_lt = fminf(fmaxf(d_lt1, 0.0f), d);
        const float t_tot = fmaf(d - d_lt, 1.0f / S_MAX, t_lt);

        // T[round(tof)-1] = 0.1 * round(tof)
        const float Tt = 0.1f * rintf(tof);

        const float p = fast_sigmoid(SIG_K * (Tt - t_tot));

        r = lowHalf ? (rec * p) : (1.0f - p);
    }

    // Mixed-op butterfly within 16-lane halves.
    #pragma unroll
    for (int o = 8; o > 0; o >>= 1) {
        const float t = __shfl_xor_sync(0xFFFFFFFFu, r, o);
        r = lowHalf ? (r + t) : (r * t);
    }
    // lane 0 holds sum(s); lane 16 holds prod(q). Pair them.
    const float t = __shfl_xor_sync(0xFFFFFFFFu, r, 16);

    if (lane == 0) out[b] = fmaf(r, t, 0.001f);
}

extern "C" void kernel_launch(void* const* d_in, const int* in_sizes, int n_in,
                              void* d_out, int out_size) {
    comp_prob_kernel<<<1, 256>>>((const float*)d_in[0], (float*)d_out);
}

// round 17
// speedup vs baseline: 1.1835x; 1.1835x over previous
#include <cuda_runtime.h>
#include <math.h>

#define C_B  8
#define C_J  22
#define C_F  14
#define A_MAX 7.25f
#define S_MAX 9.25f
#define SIG_K (3.14f / (1.732f * 0.5f))

// FINAL CHAMPION — record holder (bench 5.088us, R13). Single CTA, 256
// threads, warp b = batch b. Lane layout:
//   lanes 0..10  : attacker j=lane    -> r = rec_j * p_j  (sum half)
//   lanes 16..26 : defender j=lane-5  -> r = 1 - p_j      (product half)
//   lanes 11..15 neutral 0, lanes 27..31 neutral 1.
// Mixed-op butterfly: 4 levels inside each 16-lane half (add low / mul
// high) + one cross-half shuffle = 5 SHFLs for the full (sum, product)
// reduction. Sigmoid = 0.5*tanh.approx(x/2)+0.5 (single MUFU trip).
// Floor model (validated R12-R16, 5 identical-binary samples): ~3.3us
// launch/ramp + ~0.4us cold DRAM round-trip + ~0.5us work. Noise: ncu
// [4.35,4.86], bench [5.09,6.05]. Measured rejections: multi-CTA (+1.0us),
// 4 heavy warps (+1.1us); all other variants sub-noise. Do not mutate.
__device__ __forceinline__ float fast_sigmoid(float x) {
    float t;
    asm("tanh.approx.f32 %0, %1;" : "=f"(t) : "f"(0.5f * x));
    return fmaf(0.5f, t, 0.5f);
}

__global__ void __launch_bounds__(256, 1)
comp_prob_kernel(const float* __restrict__ frame, float* __restrict__ out) {
    const int b    = threadIdx.x >> 5;   // warp = batch
    const int lane = threadIdx.x & 31;
    const bool lowHalf = lane < 16;
    // player index: attackers 0..10 in lanes 0..10, defenders 11..21 in 16..26
    const int j = lowHalf ? lane : (lane - 5);
    const bool active = lowHalf ? (lane < 11) : (lane < 27);

    const float* row0 = frame + b * C_J * C_F;

    float r = lowHalf ? 0.0f : 1.0f;   // neutral: add-identity / mul-identity

    if (active) {
        const float* row = row0 + j * C_F;

        const float px = __ldg(row + 1), py = __ldg(row + 2);
        const float vx = __ldg(row + 3), vy = __ldg(row + 4);
        const float rec = lowHalf ? __ldg(row + 10) : 0.0f;
        const float bxf = __ldg(row0 + 11);
        const float byf = __ldg(row0 + 12);
        const float tof = __ldg(row0 + 13);

        // Selected field cell: x = int(bx)+0.5, y = (int(by)+1)-0.5
        const float fx = (float)((int)bxf) + 0.5f;
        const float fy = (float)((int)byf) + 0.5f;

        const float dx = fx - px;
        const float dy = fy - py;
        const float d2 = fmaf(dx, dx, dy * dy);
        const float invd = rsqrtf(d2);
        const float d = d2 * invd;

        float s0 = fmaf(dx, vx, dy * vy) * invd;
        s0 = fminf(fmaxf(s0, -S_MAX), S_MAX);

        // Arm A: reaches top speed
        const float t_lt1 = (S_MAX - s0) * (1.0f / A_MAX);
        const float d_lt1 = t_lt1 * (s0 + S_MAX) * 0.5f;
        // Arm B: doesn't
        const float sa = s0 * (1.0f / A_MAX);
        const float t_lt2 = sqrtf(fmaf(sa, sa, 2.0f * d * (1.0f / A_MAX))) - sa;

        const float t_lt = (d_lt1 > d) ? t_lt2 : t_lt1;
        const float d_lt = fminf(fmaxf(d_lt1, 0.0f), d);
        const float t_tot = fmaf(d - d_lt, 1.0f / S_MAX, t_lt);

        // T[round(tof)-1] = 0.1 * round(tof)
        const float Tt = 0.1f * rintf(tof);

        const float p = fast_sigmoid(SIG_K * (Tt - t_tot));

        r = lowHalf ? (rec * p) : (1.0f - p);
    }

    // Mixed-op butterfly within 16-lane halves.
    #pragma unroll
    for (int o = 8; o > 0; o >>= 1) {
        const float t = __shfl_xor_sync(0xFFFFFFFFu, r, o);
        r = lowHalf ? (r + t) : (r * t);
    }
    // lane 0 holds sum(s); lane 16 holds prod(q). Pair them.
    const float t = __shfl_xor_sync(0xFFFFFFFFu, r, 16);

    if (lane == 0) out[b] = fmaf(r, t, 0.001f);
}

extern "C" void kernel_launch(void* const* d_in, const int* in_sizes, int n_in,
                              void* d_out, int out_size) {
    comp_prob_kernel<<<1, 256>>>((const float*)d_in[0], (float*)d_out);
}